// round 16
// baseline (speedup 1.0000x reference)
#include <cuda_runtime.h>
#include <cuda_fp16.h>
#include <cstdint>

// shapes
#define NEF   64
#define NNF   128
#define NGF   64
#define IN_CH 384      // 24 k-steps of 16 = 6 chunks of 64 k
#define HID   128
#define TGT   64
#define TILE_E 64      // 4 warps x 16 rows

// W fragments fp16, packed per (kstep, ntile-pair, lane): uint4
__device__ uint4 g_w1f4[24 * 8 * 32];   // 96 KB
__device__ uint4 g_w2f4[8 * 4 * 32];    // 16 KB

__device__ __forceinline__ uint32_t f16x2(float x0, float x1) {
    uint32_t r; asm("cvt.rn.f16x2.f32 %0, %1, %2;" : "=r"(r) : "f"(x1), "f"(x0)); return r;
}

#define MMA(d, a0, a1, a2, a3, b0, b1) \
    asm volatile("mma.sync.aligned.m16n8k16.row.col.f32.f16.f16.f32 " \
        "{%0,%1,%2,%3}, {%4,%5,%6,%7}, {%8,%9}, {%0,%1,%2,%3};" \
        : "+f"((d)[0]), "+f"((d)[1]), "+f"((d)[2]), "+f"((d)[3]) \
        : "r"(a0), "r"(a1), "r"(a2), "r"(a3), "r"(b0), "r"(b1))

// ---- prep: pack weights into uint4 fragment order (once per launch) ----
__global__ void prep_frags(const float* __restrict__ W1, const float* __restrict__ W2) {
    int i = blockIdx.x * blockDim.x + threadIdx.x;
    if (i < 24 * 8 * 32) {
        int lane = i & 31, ntp = (i >> 5) & 7, ks = i >> 8;
        int qn = lane >> 2;
        int n0 = (2 * ntp) * 8 + qn;
        int n1 = (2 * ntp + 1) * 8 + qn;
        int k0 = ks * 16 + (lane & 3) * 2;
        uint4 v;
        v.x = f16x2(W1[(size_t)k0 * HID + n0],       W1[(size_t)(k0 + 1) * HID + n0]);
        v.y = f16x2(W1[(size_t)(k0 + 8) * HID + n0], W1[(size_t)(k0 + 9) * HID + n0]);
        v.z = f16x2(W1[(size_t)k0 * HID + n1],       W1[(size_t)(k0 + 1) * HID + n1]);
        v.w = f16x2(W1[(size_t)(k0 + 8) * HID + n1], W1[(size_t)(k0 + 9) * HID + n1]);
        g_w1f4[i] = v;
    } else if (i < 24 * 8 * 32 + 8 * 4 * 32) {
        int j = i - 24 * 8 * 32;
        int lane = j & 31, ntp = (j >> 5) & 3, ks = j >> 7;
        int qn = lane >> 2;
        int n0 = (2 * ntp) * 8 + qn;
        int n1 = (2 * ntp + 1) * 8 + qn;
        int k0 = ks * 16 + (lane & 3) * 2;
        uint4 v;
        v.x = f16x2(W2[(size_t)k0 * TGT + n0],       W2[(size_t)(k0 + 1) * TGT + n0]);
        v.y = f16x2(W2[(size_t)(k0 + 8) * TGT + n0], W2[(size_t)(k0 + 9) * TGT + n0]);
        v.z = f16x2(W2[(size_t)k0 * TGT + n1],       W2[(size_t)(k0 + 1) * TGT + n1]);
        v.w = f16x2(W2[(size_t)(k0 + 8) * TGT + n1], W2[(size_t)(k0 + 9) * TGT + n1]);
        g_w2f4[j] = v;
    }
}

// ---- stage one 16-row x 64-k chunk into warp-private swizzled SMEM (f16) ----
// layout: row*128 + ((g16 ^ (row&7))<<4), g16 = 16B group (8 f16) within row
__device__ __forceinline__ void stage_rows(unsigned char* wb, const float* __restrict__ src,
                                           int stride, int coff, int ebase, int E, int lane) {
    float4 va[4], vb[4];
    #pragma unroll
    for (int j = 0; j < 4; ++j) {
        int il = lane + j * 32;
        int rl = il >> 3, g = il & 7;
        int e = ebase + rl; if (e >= E) e = E - 1;
        const float* p = src + (size_t)e * stride + coff + g * 8;
        va[j] = *(const float4*)p;
        vb[j] = *(const float4*)(p + 4);
    }
    #pragma unroll
    for (int j = 0; j < 4; ++j) {
        int il = lane + j * 32;
        int rl = il >> 3, g = il & 7;
        uint4 h;
        h.x = f16x2(va[j].x, va[j].y); h.y = f16x2(va[j].z, va[j].w);
        h.z = f16x2(vb[j].x, vb[j].y); h.w = f16x2(vb[j].z, vb[j].w);
        *(uint4*)(wb + rl * 128 + ((g ^ (rl & 7)) << 4)) = h;
    }
}

__device__ __forceinline__ void stage_rows_u(unsigned char* wb, const float* __restrict__ u,
                                             const int* b32p, const long long* b64p, bool is64,
                                             int ebase, int E, int lane) {
    float4 va[4], vb[4];
    #pragma unroll
    for (int j = 0; j < 4; ++j) {
        int il = lane + j * 32;
        int rl = il >> 3, g = il & 7;
        int e = ebase + rl; if (e >= E) e = E - 1;
        long long gi = is64 ? b64p[e] : (long long)b32p[e];
        const float* p = u + (size_t)gi * NGF + g * 8;
        va[j] = *(const float4*)p;
        vb[j] = *(const float4*)(p + 4);
    }
    #pragma unroll
    for (int j = 0; j < 4; ++j) {
        int il = lane + j * 32;
        int rl = il >> 3, g = il & 7;
        uint4 h;
        h.x = f16x2(va[j].x, va[j].y); h.y = f16x2(va[j].z, va[j].w);
        h.z = f16x2(vb[j].x, vb[j].y); h.w = f16x2(vb[j].z, vb[j].w);
        *(uint4*)(wb + rl * 128 + ((g ^ (rl & 7)) << 4)) = h;
    }
}

// one k-step: 4 conflict-free LDS.32 for A (already f16x2), 8 LDG.128 for B, 16 MMAs
#define KSTEP_S(WB, KSL, KS) do { \
    uint32_t a0 = *(const uint32_t*)((WB) + qr * 128       + ((((KSL)*2)   ^ qr) << 4) + cb2); \
    uint32_t a1 = *(const uint32_t*)((WB) + (qr + 8) * 128 + ((((KSL)*2)   ^ qr) << 4) + cb2); \
    uint32_t a2 = *(const uint32_t*)((WB) + qr * 128       + ((((KSL)*2+1) ^ qr) << 4) + cb2); \
    uint32_t a3 = *(const uint32_t*)((WB) + (qr + 8) * 128 + ((((KSL)*2+1) ^ qr) << 4) + cb2); \
    const uint4* wp = g_w1f4 + (KS) * 256 + lane; \
    uint4 b0 = __ldg(wp);       uint4 b1 = __ldg(wp + 32); \
    uint4 b2 = __ldg(wp + 64);  uint4 b3 = __ldg(wp + 96); \
    MMA(acc[0], a0, a1, a2, a3, b0.x, b0.y); MMA(acc[1], a0, a1, a2, a3, b0.z, b0.w); \
    MMA(acc[2], a0, a1, a2, a3, b1.x, b1.y); MMA(acc[3], a0, a1, a2, a3, b1.z, b1.w); \
    MMA(acc[4], a0, a1, a2, a3, b2.x, b2.y); MMA(acc[5], a0, a1, a2, a3, b2.z, b2.w); \
    MMA(acc[6], a0, a1, a2, a3, b3.x, b3.y); MMA(acc[7], a0, a1, a2, a3, b3.z, b3.w); \
    uint4 b4 = __ldg(wp + 128); uint4 b5 = __ldg(wp + 160); \
    uint4 b6 = __ldg(wp + 192); uint4 b7 = __ldg(wp + 224); \
    MMA(acc[8],  a0, a1, a2, a3, b4.x, b4.y); MMA(acc[9],  a0, a1, a2, a3, b4.z, b4.w); \
    MMA(acc[10], a0, a1, a2, a3, b5.x, b5.y); MMA(acc[11], a0, a1, a2, a3, b5.z, b5.w); \
    MMA(acc[12], a0, a1, a2, a3, b6.x, b6.y); MMA(acc[13], a0, a1, a2, a3, b6.z, b6.w); \
    MMA(acc[14], a0, a1, a2, a3, b7.x, b7.y); MMA(acc[15], a0, a1, a2, a3, b7.z, b7.w); \
} while (0)

#define CHUNK(WB, SRC, STRIDE, COFF, KBASE) do { \
    __syncwarp(); \
    stage_rows(WB, SRC, STRIDE, COFF, ebase, E, lane); \
    __syncwarp(); \
    _Pragma("unroll") \
    for (int ksl = 0; ksl < 4; ++ksl) KSTEP_S(WB, ksl, (KBASE) + ksl); \
} while (0)

__global__ __launch_bounds__(128, 4)
void edge_mlp_hmma(const float* __restrict__ ek,
                   const float* __restrict__ vrk,
                   const float* __restrict__ vsk,
                   const float* __restrict__ u,
                   const void*  __restrict__ batchv,
                   const float* __restrict__ b1,
                   const float* __restrict__ b2,
                   float* __restrict__ out,
                   int E)
{
    __shared__ __align__(16) unsigned char xs[2][4][16 * 128];   // 16 KB, warp-private regions

    const int tid  = threadIdx.x;
    const int wid  = tid >> 5;
    const int lane = tid & 31;
    const int qr   = lane >> 2;          // row within 8
    const int cb   = (lane & 3) * 2;     // col pair base
    const int cb2  = (lane & 3) * 4;     // byte offset of f16 pair within 16B group

    const int ebase = blockIdx.x * TILE_E + wid * 16;
    int e_lo = ebase + qr;
    int e_hi = e_lo + 8;
    const bool st_lo = e_lo < E, st_hi = e_hi < E;

    // batch dtype sniff: sorted values < G=256, so int64 => high word of last elem is 0
    const int* b32p = (const int*)batchv;
    const long long* b64p = (const long long*)batchv;
    const bool is64 = (b32p[E - 1] == 0);

    unsigned char* wbA = &xs[0][wid][0];
    unsigned char* wbB = &xs[1][wid][0];

    // ---- layer 1: D1[16 rows x 128 cols] per warp ----
    float acc[16][4];
    #pragma unroll
    for (int nt = 0; nt < 16; ++nt)
        #pragma unroll
        for (int j = 0; j < 4; ++j) acc[nt][j] = 0.f;

    CHUNK(wbA, ek,  NEF, 0,  0);    // k 0..63
    CHUNK(wbB, vrk, NNF, 0,  4);    // k 64..127
    CHUNK(wbA, vrk, NNF, 64, 8);    // k 128..191
    CHUNK(wbB, vsk, NNF, 0,  12);   // k 192..255
    CHUNK(wbA, vsk, NNF, 64, 16);   // k 256..319
    {                               // k 320..383 (u gather)
        __syncwarp();
        stage_rows_u(wbB, u, b32p, b64p, is64, ebase, E, lane);
        __syncwarp();
        #pragma unroll
        for (int ksl = 0; ksl < 4; ++ksl) KSTEP_S(wbB, ksl, 20 + ksl);
    }

    // ---- epilogue 1 in registers: bias + relu + cvt -> layer-2 A fragments ----
    uint32_t hh[8][4];
    #pragma unroll
    for (int j = 0; j < 8; ++j) {
        float2 bA = *(const float2*)(b1 + 16 * j + cb);
        float2 bB = *(const float2*)(b1 + 16 * j + 8 + cb);
        float v00 = fmaxf(acc[2*j][0]   + bA.x, 0.f);
        float v01 = fmaxf(acc[2*j][1]   + bA.y, 0.f);
        float v10 = fmaxf(acc[2*j][2]   + bA.x, 0.f);
        float v11 = fmaxf(acc[2*j][3]   + bA.y, 0.f);
        float w00 = fmaxf(acc[2*j+1][0] + bB.x, 0.f);
        float w01 = fmaxf(acc[2*j+1][1] + bB.y, 0.f);
        float w10 = fmaxf(acc[2*j+1][2] + bB.x, 0.f);
        float w11 = fmaxf(acc[2*j+1][3] + bB.y, 0.f);
        hh[j][0] = f16x2(v00, v01);
        hh[j][1] = f16x2(v10, v11);
        hh[j][2] = f16x2(w00, w01);
        hh[j][3] = f16x2(w10, w11);
    }

    // ---- layer 2: D2[16 x 64] per warp, 8 n-tiles, K=128 ----
    float acc2[8][4];
    #pragma unroll
    for (int nt = 0; nt < 8; ++nt)
        #pragma unroll
        for (int j = 0; j < 4; ++j) acc2[nt][j] = 0.f;

    #pragma unroll
    for (int ks = 0; ks < 8; ++ks) {
        const uint4* wp = g_w2f4 + ks * 128 + lane;
        uint4 c0 = __ldg(wp);      uint4 c1 = __ldg(wp + 32);
        uint4 c2 = __ldg(wp + 64); uint4 c3 = __ldg(wp + 96);
        MMA(acc2[0], hh[ks][0], hh[ks][1], hh[ks][2], hh[ks][3], c0.x, c0.y);
        MMA(acc2[1], hh[ks][0], hh[ks][1], hh[ks][2], hh[ks][3], c0.z, c0.w);
        MMA(acc2[2], hh[ks][0], hh[ks][1], hh[ks][2], hh[ks][3], c1.x, c1.y);
        MMA(acc2[3], hh[ks][0], hh[ks][1], hh[ks][2], hh[ks][3], c1.z, c1.w);
        MMA(acc2[4], hh[ks][0], hh[ks][1], hh[ks][2], hh[ks][3], c2.x, c2.y);
        MMA(acc2[5], hh[ks][0], hh[ks][1], hh[ks][2], hh[ks][3], c2.z, c2.w);
        MMA(acc2[6], hh[ks][0], hh[ks][1], hh[ks][2], hh[ks][3], c3.x, c3.y);
        MMA(acc2[7], hh[ks][0], hh[ks][1], hh[ks][2], hh[ks][3], c3.z, c3.w);
    }

    // ---- store: + b2 ----
    #pragma unroll
    for (int nt = 0; nt < 8; ++nt) {
        float2 bb = *(const float2*)(b2 + nt * 8 + cb);
        if (st_lo)
            *(float2*)(out + (size_t)e_lo * TGT + nt * 8 + cb) =
                make_float2(acc2[nt][0] + bb.x, acc2[nt][1] + bb.y);
        if (st_hi)
            *(float2*)(out + (size_t)e_hi * TGT + nt * 8 + cb) =
                make_float2(acc2[nt][2] + bb.x, acc2[nt][3] + bb.y);
    }
}

extern "C" void kernel_launch(void* const* d_in, const int* in_sizes, int n_in,
                              void* d_out, int out_size)
{
    const float* ek    = (const float*)d_in[0];
    const float* vrk   = (const float*)d_in[1];
    const float* vsk   = (const float*)d_in[2];
    const float* u     = (const float*)d_in[3];
    const void*  batch = (const void*) d_in[4];
    const float* W1    = (const float*)d_in[5];
    const float* b1    = (const float*)d_in[6];
    const float* W2    = (const float*)d_in[7];
    const float* b2    = (const float*)d_in[8];
    float* out = (float*)d_out;

    const int E = in_sizes[0] / NEF;

    prep_frags<<<(24 * 8 * 32 + 8 * 4 * 32 + 255) / 256, 256>>>(W1, W2);

    const int grid = (E + TILE_E - 1) / TILE_E;
    edge_mlp_hmma<<<grid, 128>>>(ek, vrk, vsk, u, batch, b1, b2, out, E);
}

// round 17
// speedup vs baseline: 1.1377x; 1.1377x over previous
#include <cuda_runtime.h>
#include <cuda_fp16.h>
#include <cstdint>

// shapes
#define NEF   64
#define NNF   128
#define NGF   64
#define IN_CH 384      // 24 k-steps of 16
#define HID   128
#define TGT   64
#define TILE_E 64      // 4 warps x 16 rows

// W fragments fp16, packed per (kstep, ntile-pair, lane): uint4
// k within a kstep is PERMUTED so A loads are contiguous float4 per lane:
// lane c (=lane&3) covers gmem cols ks*16+4c..4c+3 -> MMA-k {2c,2c+1} (b0/a0) and {2c+8,2c+9} (b1/a2)
__device__ uint4 g_w1f4[24 * 8 * 32];   // 96 KB
__device__ uint4 g_w2f4[8 * 4 * 32];    // 16 KB

__device__ __forceinline__ uint32_t f16x2(float x0, float x1) {
    uint32_t r; asm("cvt.rn.f16x2.f32 %0, %1, %2;" : "=r"(r) : "f"(x1), "f"(x0)); return r;
}

#define MMA(d, a0, a1, a2, a3, b0, b1) \
    asm volatile("mma.sync.aligned.m16n8k16.row.col.f32.f16.f16.f32 " \
        "{%0,%1,%2,%3}, {%4,%5,%6,%7}, {%8,%9}, {%0,%1,%2,%3};" \
        : "+f"((d)[0]), "+f"((d)[1]), "+f"((d)[2]), "+f"((d)[3]) \
        : "r"(a0), "r"(a1), "r"(a2), "r"(a3), "r"(b0), "r"(b1))

// ---- prep: pack weights into uint4 fragment order (once per launch) ----
__global__ void prep_frags(const float* __restrict__ W1, const float* __restrict__ W2) {
    int i = blockIdx.x * blockDim.x + threadIdx.x;
    if (i < 24 * 8 * 32) {
        int lane = i & 31, ntp = (i >> 5) & 7, ks = i >> 8;
        int qn = lane >> 2;
        int n0 = (2 * ntp) * 8 + qn;
        int n1 = (2 * ntp + 1) * 8 + qn;
        int kg = ks * 16 + (lane & 3) * 4;   // permuted: contiguous 4 gmem cols per lane
        uint4 v;
        v.x = f16x2(W1[(size_t)kg * HID + n0],       W1[(size_t)(kg + 1) * HID + n0]);
        v.y = f16x2(W1[(size_t)(kg + 2) * HID + n0], W1[(size_t)(kg + 3) * HID + n0]);
        v.z = f16x2(W1[(size_t)kg * HID + n1],       W1[(size_t)(kg + 1) * HID + n1]);
        v.w = f16x2(W1[(size_t)(kg + 2) * HID + n1], W1[(size_t)(kg + 3) * HID + n1]);
        g_w1f4[i] = v;
    } else if (i < 24 * 8 * 32 + 8 * 4 * 32) {
        // layer 2: A comes from in-register C-fragments (no permutation possible) - standard layout
        int j = i - 24 * 8 * 32;
        int lane = j & 31, ntp = (j >> 5) & 3, ks = j >> 7;
        int qn = lane >> 2;
        int n0 = (2 * ntp) * 8 + qn;
        int n1 = (2 * ntp + 1) * 8 + qn;
        int k0 = ks * 16 + (lane & 3) * 2;
        uint4 v;
        v.x = f16x2(W2[(size_t)k0 * TGT + n0],       W2[(size_t)(k0 + 1) * TGT + n0]);
        v.y = f16x2(W2[(size_t)(k0 + 8) * TGT + n0], W2[(size_t)(k0 + 9) * TGT + n0]);
        v.z = f16x2(W2[(size_t)k0 * TGT + n1],       W2[(size_t)(k0 + 1) * TGT + n1]);
        v.w = f16x2(W2[(size_t)(k0 + 8) * TGT + n1], W2[(size_t)(k0 + 9) * TGT + n1]);
        g_w2f4[j] = v;
    }
}

// one k-step of layer 1: 2 contiguous LDG.128 for A (permuted k), 8 LDG.128 for B, 16 MMAs
#define KSTEP(RLO, RHI, C4, KS) do { \
    float4 xlo = *(const float4*)((RLO) + (C4)); \
    float4 xhi = *(const float4*)((RHI) + (C4)); \
    const uint4* wp = g_w1f4 + (KS) * 256 + lane; \
    uint4 b0 = __ldg(wp);      uint4 b1 = __ldg(wp + 32); \
    uint4 b2 = __ldg(wp + 64); uint4 b3 = __ldg(wp + 96); \
    uint32_t a0 = f16x2(xlo.x, xlo.y); uint32_t a2 = f16x2(xlo.z, xlo.w); \
    uint32_t a1 = f16x2(xhi.x, xhi.y); uint32_t a3 = f16x2(xhi.z, xhi.w); \
    MMA(acc[0], a0, a1, a2, a3, b0.x, b0.y); MMA(acc[1], a0, a1, a2, a3, b0.z, b0.w); \
    MMA(acc[2], a0, a1, a2, a3, b1.x, b1.y); MMA(acc[3], a0, a1, a2, a3, b1.z, b1.w); \
    MMA(acc[4], a0, a1, a2, a3, b2.x, b2.y); MMA(acc[5], a0, a1, a2, a3, b2.z, b2.w); \
    MMA(acc[6], a0, a1, a2, a3, b3.x, b3.y); MMA(acc[7], a0, a1, a2, a3, b3.z, b3.w); \
    uint4 b4 = __ldg(wp + 128); uint4 b5 = __ldg(wp + 160); \
    uint4 b6 = __ldg(wp + 192); uint4 b7 = __ldg(wp + 224); \
    MMA(acc[8],  a0, a1, a2, a3, b4.x, b4.y); MMA(acc[9],  a0, a1, a2, a3, b4.z, b4.w); \
    MMA(acc[10], a0, a1, a2, a3, b5.x, b5.y); MMA(acc[11], a0, a1, a2, a3, b5.z, b5.w); \
    MMA(acc[12], a0, a1, a2, a3, b6.x, b6.y); MMA(acc[13], a0, a1, a2, a3, b6.z, b6.w); \
    MMA(acc[14], a0, a1, a2, a3, b7.x, b7.y); MMA(acc[15], a0, a1, a2, a3, b7.z, b7.w); \
} while (0)

__global__ __launch_bounds__(128, 4)
void edge_mlp_hmma(const float* __restrict__ ek,
                   const float* __restrict__ vrk,
                   const float* __restrict__ vsk,
                   const float* __restrict__ u,
                   const void*  __restrict__ batchv,
                   const float* __restrict__ b1,
                   const float* __restrict__ b2,
                   float* __restrict__ out,
                   int E)
{
    const int tid  = threadIdx.x;
    const int wid  = tid >> 5;
    const int lane = tid & 31;
    const int qr   = lane >> 2;        // row within 8
    const int cb   = (lane & 3) * 2;   // col pair base (output/C-frag)
    const int c4   = (lane & 3) * 4;   // contiguous A-load base within kstep

    int e_lo = blockIdx.x * TILE_E + wid * 16 + qr;
    int e_hi = e_lo + 8;
    const bool st_lo = e_lo < E, st_hi = e_hi < E;
    const int el = st_lo ? e_lo : E - 1;
    const int eh = st_hi ? e_hi : E - 1;

    // batch dtype sniff: sorted values < G=256, so int64 => high word of last elem is 0
    const int* b32p = (const int*)batchv;
    const long long* b64p = (const long long*)batchv;
    const bool is64 = (b32p[E - 1] == 0);
    const long long g_lo = is64 ? b64p[el] : (long long)b32p[el];
    const long long g_hi = is64 ? b64p[eh] : (long long)b32p[eh];

    const float* ek_lo = ek  + (size_t)el * NEF;
    const float* ek_hi = ek  + (size_t)eh * NEF;
    const float* vr_lo = vrk + (size_t)el * NNF;
    const float* vr_hi = vrk + (size_t)eh * NNF;
    const float* vs_lo = vsk + (size_t)el * NNF;
    const float* vs_hi = vsk + (size_t)eh * NNF;
    const float* u_lo  = u   + (size_t)g_lo * NGF;
    const float* u_hi  = u   + (size_t)g_hi * NGF;

    // ---- layer 1: D1[16 rows x 128 cols] per warp ----
    float acc[16][4];
    #pragma unroll
    for (int nt = 0; nt < 16; ++nt)
        #pragma unroll
        for (int j = 0; j < 4; ++j) acc[nt][j] = 0.f;

    #pragma unroll
    for (int ks = 0; ks < 4; ++ks) KSTEP(ek_lo, ek_hi, ks * 16 + c4, ks);
    #pragma unroll
    for (int ks = 0; ks < 8; ++ks) KSTEP(vr_lo, vr_hi, ks * 16 + c4, ks + 4);
    #pragma unroll
    for (int ks = 0; ks < 8; ++ks) KSTEP(vs_lo, vs_hi, ks * 16 + c4, ks + 12);
    #pragma unroll
    for (int ks = 0; ks < 4; ++ks) KSTEP(u_lo, u_hi, ks * 16 + c4, ks + 20);

    // ---- epilogue 1 in registers: bias + relu + cvt -> layer-2 A fragments ----
    // C-frag (m16n8) layout == A-frag (m16n8k16) layout: nt pair (2j, 2j+1) => k-step j
    uint32_t hh[8][4];
    #pragma unroll
    for (int j = 0; j < 8; ++j) {
        float2 bA = *(const float2*)(b1 + 16 * j + cb);
        float2 bB = *(const float2*)(b1 + 16 * j + 8 + cb);
        float v00 = fmaxf(acc[2*j][0]   + bA.x, 0.f);
        float v01 = fmaxf(acc[2*j][1]   + bA.y, 0.f);
        float v10 = fmaxf(acc[2*j][2]   + bA.x, 0.f);
        float v11 = fmaxf(acc[2*j][3]   + bA.y, 0.f);
        float w00 = fmaxf(acc[2*j+1][0] + bB.x, 0.f);
        float w01 = fmaxf(acc[2*j+1][1] + bB.y, 0.f);
        float w10 = fmaxf(acc[2*j+1][2] + bB.x, 0.f);
        float w11 = fmaxf(acc[2*j+1][3] + bB.y, 0.f);
        hh[j][0] = f16x2(v00, v01);
        hh[j][1] = f16x2(v10, v11);
        hh[j][2] = f16x2(w00, w01);
        hh[j][3] = f16x2(w10, w11);
    }

    // ---- layer 2: D2[16 x 64] per warp, 8 n-tiles, K=128 (8 k-steps) ----
    float acc2[8][4];
    #pragma unroll
    for (int nt = 0; nt < 8; ++nt)
        #pragma unroll
        for (int j = 0; j < 4; ++j) acc2[nt][j] = 0.f;

    #pragma unroll
    for (int ks = 0; ks < 8; ++ks) {
        const uint4* wp = g_w2f4 + ks * 128 + lane;
        uint4 c0 = __ldg(wp);      uint4 c1 = __ldg(wp + 32);
        uint4 c2 = __ldg(wp + 64); uint4 c3 = __ldg(wp + 96);
        MMA(acc2[0], hh[ks][0], hh[ks][1], hh[ks][2], hh[ks][3], c0.x, c0.y);
        MMA(acc2[1], hh[ks][0], hh[ks][1], hh[ks][2], hh[ks][3], c0.z, c0.w);
        MMA(acc2[2], hh[ks][0], hh[ks][1], hh[ks][2], hh[ks][3], c1.x, c1.y);
        MMA(acc2[3], hh[ks][0], hh[ks][1], hh[ks][2], hh[ks][3], c1.z, c1.w);
        MMA(acc2[4], hh[ks][0], hh[ks][1], hh[ks][2], hh[ks][3], c2.x, c2.y);
        MMA(acc2[5], hh[ks][0], hh[ks][1], hh[ks][2], hh[ks][3], c2.z, c2.w);
        MMA(acc2[6], hh[ks][0], hh[ks][1], hh[ks][2], hh[ks][3], c3.x, c3.y);
        MMA(acc2[7], hh[ks][0], hh[ks][1], hh[ks][2], hh[ks][3], c3.z, c3.w);
    }

    // ---- store: + b2 ----
    #pragma unroll
    for (int nt = 0; nt < 8; ++nt) {
        float2 bb = *(const float2*)(b2 + nt * 8 + cb);
        if (st_lo)
            *(float2*)(out + (size_t)e_lo * TGT + nt * 8 + cb) =
                make_float2(acc2[nt][0] + bb.x, acc2[nt][1] + bb.y);
        if (st_hi)
            *(float2*)(out + (size_t)e_hi * TGT + nt * 8 + cb) =
                make_float2(acc2[nt][2] + bb.x, acc2[nt][3] + bb.y);
    }
}

extern "C" void kernel_launch(void* const* d_in, const int* in_sizes, int n_in,
                              void* d_out, int out_size)
{
    const float* ek    = (const float*)d_in[0];
    const float* vrk   = (const float*)d_in[1];
    const float* vsk   = (const float*)d_in[2];
    const float* u     = (const float*)d_in[3];
    const void*  batch = (const void*) d_in[4];
    const float* W1    = (const float*)d_in[5];
    const float* b1    = (const float*)d_in[6];
    const float* W2    = (const float*)d_in[7];
    const float* b2    = (const float*)d_in[8];
    float* out = (float*)d_out;

    const int E = in_sizes[0] / NEF;

    prep_frags<<<(24 * 8 * 32 + 8 * 4 * 32 + 255) / 256, 256>>>(W1, W2);

    const int grid = (E + TILE_E - 1) / TILE_E;
    edge_mlp_hmma<<<grid, 128>>>(ek, vrk, vsk, u, batch, b1, b2, out, E);
}